// round 3
// baseline (speedup 1.0000x reference)
#include <cuda_runtime.h>

#define BN   16
#define C    256
#define H    56
#define W    56
#define OC   256
#define HW   (H*W)        // 3136
#define NPIX (BN*HW)      // 50176
#define ICW  64           // int32 words per pixel (256 ch / 4)

#define OCT  128          // oc per block
#define PXT  28           // pixels per block (half row)
#define CW   8            // icw words per ic-chunk (32 channels)
#define NCHUNK (ICW/CW)   // 8
#define WSTR (9*CW + 4)   // 76 ints per oc in smem (pad -> conflict-free)

#define X_ELEMS  (BN*C*H*W)     // 12845056
#define W_ELEMS  (OC*C*3*3)     // 589824
#define B_ELEMS  (OC)           // 256

// Packed int8 scratch (device globals: allocation-free rule)
__device__ int g_xp[NPIX * ICW];     // [pix][icw], each int = 4 channels int8
__device__ int g_wp[OC * 9 * ICW];   // [oc][tap][icw]

__global__ void pack_x_kernel(const int* __restrict__ x) {
    int idx = blockIdx.x * blockDim.x + threadIdx.x;
    if (idx >= NPIX * ICW) return;
    int pix = idx % NPIX;          // consecutive threads -> consecutive pixels (coalesced reads)
    int icw = idx / NPIX;
    int w = pix % W;
    int t = pix / W;
    int h = t % H;
    int b = t / H;
    int c0 = icw * 4;
    const int* p = x + ((b * C + c0) * H + h) * W + w;
    int v0 = p[0];
    int v1 = p[HW];
    int v2 = p[2 * HW];
    int v3 = p[3 * HW];
    // values in [0,127): fit positively in int8, no masking needed
    g_xp[pix * ICW + icw] = v0 | (v1 << 8) | (v2 << 16) | (v3 << 24);
}

__global__ void pack_w_kernel(const int* __restrict__ wsrc) {
    int idx = blockIdx.x * blockDim.x + threadIdx.x;
    if (idx >= OC * 9 * ICW) return;
    int icw = idx % ICW;
    int t   = idx / ICW;
    int tap = t % 9;
    int oc  = t / 9;
    int c0 = icw * 4;
    const int* p = wsrc + (oc * C + c0) * 9 + tap;   // OIHW, taps contiguous per ic
    int v0 = p[0];
    int v1 = p[9];
    int v2 = p[18];
    int v3 = p[27];
    g_wp[(oc * 9 + tap) * ICW + icw] = v0 | (v1 << 8) | (v2 << 16) | (v3 << 24);
}

__global__ __launch_bounds__(224) void conv_kernel(const int* __restrict__ bias,
                                                   float* __restrict__ out) {
    __shared__ __align__(16) int sw[OCT * WSTR];   // 128*76 = 9728 ints = 38912 B
    __shared__ __align__(16) int sx[3 * 30 * CW];  // 720 ints

    const int lane = threadIdx.x;         // 0..31 -> oc lane
    const int py   = threadIdx.y;         // 0..6  -> px group (4 px each)
    const int tid  = py * 32 + lane;

    const int bx  = blockIdx.x;
    const int pxt = bx & 1;
    const int r   = bx >> 1;
    const int h   = r % H;
    const int b   = r / H;
    const int w0  = pxt * PXT;
    const int oc_base = blockIdx.y * OCT;

    int acc[4][4];
    #pragma unroll
    for (int o = 0; o < 4; o++)
        #pragma unroll
        for (int p = 0; p < 4; p++) acc[o][p] = 0;

    for (int ch = 0; ch < NCHUNK; ch++) {
        // ---- stage weights: 128 oc x 9 taps x 8 words ----
        for (int t = tid; t < OCT * 9 * CW; t += 224) {
            int i  = t % (9 * CW);                 // 0..71
            int oc = t / (9 * CW);
            int tap = i / CW;
            int k   = i % CW;
            sw[oc * WSTR + i] = g_wp[(oc_base + oc) * (9 * ICW) + tap * ICW + ch * CW + k];
        }
        // ---- stage x: 3 rows x 30 cols x 8 words, zero-pad OOB ----
        for (int t = tid; t < 3 * 30 * CW; t += 224) {
            int k   = t % CW;
            int col = (t / CW) % 30;
            int row = t / (30 * CW);
            int hin = h - 1 + row;
            int win = w0 - 1 + col;
            int v = 0;
            if ((unsigned)hin < (unsigned)H && (unsigned)win < (unsigned)W) {
                int pix = (b * H + hin) * W + win;
                v = g_xp[pix * ICW + ch * CW + k];
            }
            sx[t] = v;
        }
        __syncthreads();

        // ---- compute: 4 oc x 4 px register tile, dp4a ----
        #pragma unroll
        for (int kh = 0; kh < 3; kh++) {
            #pragma unroll
            for (int kw = 0; kw < 3; kw++) {
                const int tap = kh * 3 + kw;
                #pragma unroll
                for (int iq = 0; iq < CW / 4; iq++) {
                    int4 xv[4];
                    #pragma unroll
                    for (int p = 0; p < 4; p++) {
                        int col = py * 4 + p + kw;
                        xv[p] = *(const int4*)&sx[(kh * 30 + col) * CW + iq * 4];
                    }
                    #pragma unroll
                    for (int o = 0; o < 4; o++) {
                        int4 wv = *(const int4*)&sw[(lane + 32 * o) * WSTR + tap * CW + iq * 4];
                        #pragma unroll
                        for (int p = 0; p < 4; p++) {
                            acc[o][p] = __dp4a(xv[p].x, wv.x, acc[o][p]);
                            acc[o][p] = __dp4a(xv[p].y, wv.y, acc[o][p]);
                            acc[o][p] = __dp4a(xv[p].z, wv.z, acc[o][p]);
                            acc[o][p] = __dp4a(xv[p].w, wv.w, acc[o][p]);
                        }
                    }
                }
            }
        }
        __syncthreads();
    }

    // ---- epilogue: +bias, convert to float32 (metadata __output__ dtype), float4 stores ----
    const int wout = w0 + py * 4;
    #pragma unroll
    for (int o = 0; o < 4; o++) {
        int oc = oc_base + lane + 32 * o;
        int bv = bias[oc];
        float4 v = make_float4((float)(acc[o][0] + bv), (float)(acc[o][1] + bv),
                               (float)(acc[o][2] + bv), (float)(acc[o][3] + bv));
        *(float4*)&out[((b * OC + oc) * H + h) * W + wout] = v;
    }
}

extern "C" void kernel_launch(void* const* d_in, const int* in_sizes, int n_in,
                              void* d_out, int out_size) {
    // Bind inputs by element count (robust to metadata ordering):
    //   x: 16*256*56*56 = 12845056, w: 256*256*3*3 = 589824, bias: 256
    const int* x    = nullptr;
    const int* wsrc = nullptr;
    const int* bias = nullptr;
    for (int i = 0; i < n_in; i++) {
        if (in_sizes[i] == X_ELEMS)      x    = (const int*)d_in[i];
        else if (in_sizes[i] == W_ELEMS) wsrc = (const int*)d_in[i];
        else if (in_sizes[i] == B_ELEMS) bias = (const int*)d_in[i];
    }
    // Fallback to positional order if sizes didn't match expectations.
    if (!x)    x    = (const int*)d_in[0];
    if (!wsrc) wsrc = (const int*)d_in[1];
    if (!bias) bias = (const int*)d_in[2];

    float* out = (float*)d_out;

    pack_x_kernel<<<(NPIX * ICW + 255) / 256, 256>>>(x);
    pack_w_kernel<<<(OC * 9 * ICW + 255) / 256, 256>>>(wsrc);

    dim3 grid(2 * H * BN, OC / OCT);   // (1792, 2)
    dim3 block(32, 7);                 // 224 threads
    conv_kernel<<<grid, block>>>(bias, out);
}

// round 5
// speedup vs baseline: 1.4217x; 1.4217x over previous
#include <cuda_runtime.h>
#include <cstdint>

#define BN   16
#define C    256
#define H    56
#define W    56
#define OC   256
#define HW   (H*W)          // 3136
#define NPIX (BN*HW)        // 50176
#define ICW  64             // int32 words per pixel (256 ch / 4)

#define X_ELEMS  (BN*C*H*W) // 12845056
#define W_ELEMS  (OC*C*3*3) // 589824
#define B_ELEMS  (OC)       // 256

#define NSTAGE 18           // 9 taps x 2 ic-planes (128 ic each)
#define MTILE  128          // output pixels per block
#define NBLK   (NPIX/MTILE) // 392

#define ASTR   36           // padded row stride in words (144B) -> conflict-free
#define A_TILE (MTILE*ASTR*4)   // 18432 B
#define B_TILE (OC*ASTR*4)      // 36864 B
#define OFF_A(buf)  ((buf)*A_TILE)
#define OFF_B(buf)  (2*A_TILE + (buf)*B_TILE)
#define OFF_BIAS    (2*A_TILE + 2*B_TILE)
#define SMEM_BYTES  (OFF_BIAS + OC*4)       // 111616

// ---- packed int8 scratch (device globals; allocation-free rule) ----
__device__ int g_xp[NPIX * ICW];          // NHWC: [pix][64 words] (4 ic per word)
__device__ int g_wp2[NSTAGE * OC * 32];   // [stage=tap*2+plane][oc][32 words]

__global__ void pack_x_kernel(const int* __restrict__ x) {
    int idx = blockIdx.x * blockDim.x + threadIdx.x;
    if (idx >= NPIX * ICW) return;
    int pix = idx % NPIX;
    int icw = idx / NPIX;
    int w = pix % W;
    int t = pix / W;
    int h = t % H;
    int b = t / H;
    int c0 = icw * 4;
    const int* p = x + ((b * C + c0) * H + h) * W + w;
    int v0 = p[0], v1 = p[HW], v2 = p[2*HW], v3 = p[3*HW];
    g_xp[pix * ICW + icw] = v0 | (v1 << 8) | (v2 << 16) | (v3 << 24);
}

__global__ void pack_w2_kernel(const int* __restrict__ wsrc) {
    int idx = blockIdx.x * blockDim.x + threadIdx.x;
    if (idx >= NSTAGE * OC * 32) return;
    int word = idx & 31;
    int oc   = (idx >> 5) & 255;
    int s    = idx >> 13;          // 0..17
    int tap  = s >> 1;
    int plane = s & 1;
    int ic0 = plane * 128 + word * 4;
    const int* p = wsrc + (oc * C + ic0) * 9 + tap;   // OIHW
    int v0 = p[0], v1 = p[9], v2 = p[18], v3 = p[27];
    g_wp2[idx] = v0 | (v1 << 8) | (v2 << 16) | (v3 << 24);
}

__device__ __forceinline__ uint32_t smem_u32(const void* p) {
    uint32_t a;
    asm("{ .reg .u64 t; cvta.to.shared.u64 t, %1; cvt.u32.u64 %0, t; }" : "=r"(a) : "l"(p));
    return a;
}

__device__ __forceinline__ void mma_s8(int* c, const int* a, const int* b) {
    asm volatile(
        "mma.sync.aligned.m16n8k32.row.col.s32.s8.s8.s32 "
        "{%0,%1,%2,%3}, {%4,%5,%6,%7}, {%8,%9}, {%0,%1,%2,%3};"
        : "+r"(c[0]), "+r"(c[1]), "+r"(c[2]), "+r"(c[3])
        : "r"(a[0]), "r"(a[1]), "r"(a[2]), "r"(a[3]), "r"(b[0]), "r"(b[1]));
}

// stage copy: A[128px x 128B] with tap shift + zero halo, B[256oc x 128B]
__device__ __forceinline__ void stage_copy(uint32_t sbase, int buf, int s,
                                           int p0, int tid) {
    const int tap = s >> 1, plane = s & 1;
    const int dh = tap / 3 - 1, dw = tap % 3 - 1;
    const uint32_t aBase = sbase + OFF_A(buf);
    #pragma unroll
    for (int it = 0; it < 4; it++) {
        int chunk = tid + it * 256;          // 0..1023
        int m = chunk >> 3, j = chunk & 7;
        int p = p0 + m;
        int b = p / HW, rem = p - b * HW;
        int h = rem / W, w = rem - h * W;
        int h2 = h + dh, w2 = w + dw;
        bool ok = ((unsigned)h2 < (unsigned)H) && ((unsigned)w2 < (unsigned)W);
        int sp = ok ? ((b * H + h2) * W + w2) : 0;
        const int* src = &g_xp[sp * ICW + plane * 32 + j * 4];
        uint32_t dst = aBase + (uint32_t)(m * (ASTR * 4) + j * 16);
        int sz = ok ? 16 : 0;                // src-size 0 -> zero-fill
        asm volatile("cp.async.cg.shared.global [%0], [%1], 16, %2;"
                     :: "r"(dst), "l"(src), "r"(sz));
    }
    const uint32_t bBase = sbase + OFF_B(buf);
    const int* wsrc = &g_wp2[s * OC * 32];
    #pragma unroll
    for (int it = 0; it < 8; it++) {
        int chunk = tid + it * 256;          // 0..2047 (oc*8 + j)
        int oc = chunk >> 3, j = chunk & 7;
        uint32_t dst = bBase + (uint32_t)(oc * (ASTR * 4) + j * 16);
        asm volatile("cp.async.cg.shared.global [%0], [%1], 16, 16;"
                     :: "r"(dst), "l"(wsrc + chunk * 4));
    }
}

__global__ __launch_bounds__(256, 1)
void conv_imma_kernel(const int* __restrict__ bias, float* __restrict__ out) {
    extern __shared__ __align__(16) char dsm[];
    const uint32_t sbase = smem_u32(dsm);
    int* sbias = (int*)(dsm + OFF_BIAS);

    const int tid = threadIdx.x;
    const int lane = tid & 31;
    const int wid  = tid >> 5;
    const int g    = lane >> 2;      // groupID 0..7
    const int tig  = lane & 3;       // thread-in-group 0..3
    const int wm   = wid & 1;        // 2 M tiles of 64 px
    const int wn   = wid >> 1;       // 4 N tiles of 64 oc
    const int p0   = blockIdx.x * MTILE;

    sbias[tid] = bias[tid];

    int acc[4][8][4];
    #pragma unroll
    for (int i = 0; i < 4; i++)
        #pragma unroll
        for (int j = 0; j < 8; j++)
            #pragma unroll
            for (int r = 0; r < 4; r++) acc[i][j][r] = 0;

    stage_copy(sbase, 0, 0, p0, tid);
    asm volatile("cp.async.commit_group;" ::: "memory");

    for (int s = 0; s < NSTAGE; s++) {
        asm volatile("cp.async.wait_group 0;" ::: "memory");
        __syncthreads();
        if (s + 1 < NSTAGE) {
            stage_copy(sbase, (s + 1) & 1, s + 1, p0, tid);
            asm volatile("cp.async.commit_group;" ::: "memory");
        }
        const int buf = s & 1;
        const int* A = (const int*)(dsm + OFF_A(buf));
        const int* B = (const int*)(dsm + OFF_B(buf));
        #pragma unroll
        for (int kq = 0; kq < 4; kq++) {
            const int koff = kq * 8;
            int a[4][4];
            #pragma unroll
            for (int i = 0; i < 4; i++) {
                int r0 = wm * 64 + i * 16 + g;
                a[i][0] = A[r0 * ASTR + koff + tig];
                a[i][1] = A[(r0 + 8) * ASTR + koff + tig];
                a[i][2] = A[r0 * ASTR + koff + 4 + tig];
                a[i][3] = A[(r0 + 8) * ASTR + koff + 4 + tig];
            }
            int bf[8][2];
            #pragma unroll
            for (int j = 0; j < 8; j++) {
                int c0 = wn * 64 + j * 8 + g;
                bf[j][0] = B[c0 * ASTR + koff + tig];
                bf[j][1] = B[c0 * ASTR + koff + 4 + tig];
            }
            #pragma unroll
            for (int i = 0; i < 4; i++)
                #pragma unroll
                for (int j = 0; j < 8; j++)
                    mma_s8(acc[i][j], a[i], bf[j]);
        }
        __syncthreads();
    }

    // epilogue: +bias, float32 out (NCHW)
    #pragma unroll
    for (int i = 0; i < 4; i++) {
        int r = wm * 64 + i * 16 + g;
        int px0 = p0 + r, px1 = px0 + 8;
        int b0 = px0 / HW, rem0 = px0 - b0 * HW;
        int b1 = px1 / HW, rem1 = px1 - b1 * HW;
        float* base0 = out + (size_t)b0 * (OC * HW) + rem0;
        float* base1 = out + (size_t)b1 * (OC * HW) + rem1;
        #pragma unroll
        for (int j = 0; j < 8; j++) {
            int oc = wn * 64 + j * 8 + tig * 2;
            int bv0 = sbias[oc], bv1 = sbias[oc + 1];
            base0[(size_t)oc * HW]        = (float)(acc[i][j][0] + bv0);
            base0[(size_t)(oc + 1) * HW]  = (float)(acc[i][j][1] + bv1);
            base1[(size_t)oc * HW]        = (float)(acc[i][j][2] + bv0);
            base1[(size_t)(oc + 1) * HW]  = (float)(acc[i][j][3] + bv1);
        }
    }
}

extern "C" void kernel_launch(void* const* d_in, const int* in_sizes, int n_in,
                              void* d_out, int out_size) {
    const int* x    = nullptr;
    const int* wsrc = nullptr;
    const int* bias = nullptr;
    for (int i = 0; i < n_in; i++) {
        if (in_sizes[i] == X_ELEMS)      x    = (const int*)d_in[i];
        else if (in_sizes[i] == W_ELEMS) wsrc = (const int*)d_in[i];
        else if (in_sizes[i] == B_ELEMS) bias = (const int*)d_in[i];
    }
    if (!x)    x    = (const int*)d_in[0];
    if (!wsrc) wsrc = (const int*)d_in[1];
    if (!bias) bias = (const int*)d_in[2];

    float* out = (float*)d_out;

    pack_x_kernel<<<(NPIX * ICW + 255) / 256, 256>>>(x);
    pack_w2_kernel<<<(NSTAGE * OC * 32 + 255) / 256, 256>>>(wsrc);

    cudaFuncSetAttribute(conv_imma_kernel,
                         cudaFuncAttributeMaxDynamicSharedMemorySize, SMEM_BYTES);
    conv_imma_kernel<<<NBLK, 256, SMEM_BYTES>>>(bias, out);
}

// round 6
// speedup vs baseline: 3.2070x; 2.2557x over previous
#include <cuda_runtime.h>
#include <cuda_bf16.h>
#include <cstdint>

#define BN   16
#define C    256
#define H    56
#define W    56
#define OC   256
#define HW   (H*W)          // 3136
#define NPIX (BN*HW)        // 50176

#define X_ELEMS  (BN*C*H*W) // 12845056
#define W_ELEMS  (OC*C*3*3) // 589824
#define B_ELEMS  (OC)       // 256

#define NSTAGE 36           // 9 taps x 4 ic-planes (64 ic each)
#define MTILE  128          // output pixels per block
#define NBLK   (NPIX/MTILE) // 392

#define RSTR   36           // padded row stride in 4B words (144B)
#define A_TILE (MTILE*144)  // 18432 B
#define B_TILE (OC*144)     // 36864 B
#define OFF_A(buf)  ((buf)*A_TILE)
#define OFF_B(buf)  (2*A_TILE + (buf)*B_TILE)
#define OFF_BIAS    (2*A_TILE + 2*B_TILE)
#define SMEM_BYTES  (OFF_BIAS + OC*4)       // 111616

// ---- packed bf16 scratch (device globals; allocation-free rule) ----
__device__ __nv_bfloat16 g_xb[NPIX * C];            // [pix][256 ic]
__device__ __nv_bfloat16 g_wb[NSTAGE * OC * 64];    // [stage][oc][64 ic]

#define XWORK (NPIX * 32)           // 8 channels per work item
#define WWORK (NSTAGE * OC * 64)    // == W_ELEMS

__global__ void pack_fused_kernel(const int* __restrict__ x,
                                  const int* __restrict__ wsrc) {
    int idx = blockIdx.x * blockDim.x + threadIdx.x;
    if (idx < XWORK) {
        int pix = idx % NPIX;
        int grp = idx / NPIX;
        int c0 = grp * 8;
        int w = pix % W;
        int t = pix / W;
        int h = t % H;
        int b = t / H;
        const int* p = x + ((b * C + c0) * H + h) * W + w;
        __align__(16) __nv_bfloat16 v[8];
        #pragma unroll
        for (int k = 0; k < 8; k++) v[k] = __float2bfloat16((float)p[k * HW]);
        *(uint4*)&g_xb[pix * C + c0] = *(const uint4*)v;
    } else if (idx < XWORK + WWORK) {
        int j = idx - XWORK;
        int i  = j & 63;
        int oc = (j >> 6) & 255;
        int s  = j >> 14;            // 0..35
        int tap = s >> 2, plane = s & 3;
        int ic = plane * 64 + i;
        g_wb[j] = __float2bfloat16((float)wsrc[(oc * C + ic) * 9 + tap]);
    }
}

__device__ __forceinline__ uint32_t smem_u32(const void* p) {
    uint32_t a;
    asm("{ .reg .u64 t; cvta.to.shared.u64 t, %1; cvt.u32.u64 %0, t; }" : "=r"(a) : "l"(p));
    return a;
}

__device__ __forceinline__ void mma_bf16(float* c, const unsigned* a, const unsigned* b) {
    asm volatile(
        "mma.sync.aligned.m16n8k16.row.col.f32.bf16.bf16.f32 "
        "{%0,%1,%2,%3}, {%4,%5,%6,%7}, {%8,%9}, {%0,%1,%2,%3};"
        : "+f"(c[0]), "+f"(c[1]), "+f"(c[2]), "+f"(c[3])
        : "r"(a[0]), "r"(a[1]), "r"(a[2]), "r"(a[3]), "r"(b[0]), "r"(b[1]));
}

// stage copy: A[128px x 64ic bf16] with tap shift + zero halo, B[256oc x 64ic]
__device__ __forceinline__ void stage_copy(uint32_t sbase, int buf, int s,
                                           int p0, int tid) {
    const int tap = s >> 2, plane = s & 3;
    const int dh = tap / 3 - 1, dw = tap % 3 - 1;
    const uint32_t aBase = sbase + OFF_A(buf);
    #pragma unroll
    for (int it = 0; it < 4; it++) {
        int chunk = tid + it * 256;          // 0..1023
        int m = chunk >> 3, j = chunk & 7;   // pixel row, 16B chunk
        int p = p0 + m;
        int b = p / HW, rem = p - b * HW;
        int h = rem / W, w = rem - h * W;
        int h2 = h + dh, w2 = w + dw;
        bool ok = ((unsigned)h2 < (unsigned)H) && ((unsigned)w2 < (unsigned)W);
        int sp = ok ? ((b * H + h2) * W + w2) : 0;
        const __nv_bfloat16* src = &g_xb[sp * C + plane * 64 + j * 8];
        uint32_t dst = aBase + (uint32_t)(m * 144 + j * 16);
        int sz = ok ? 16 : 0;                // src-size 0 -> zero-fill
        asm volatile("cp.async.cg.shared.global [%0], [%1], 16, %2;"
                     :: "r"(dst), "l"(src), "r"(sz));
    }
    const uint32_t bBase = sbase + OFF_B(buf);
    const __nv_bfloat16* ws = &g_wb[s * OC * 64];
    #pragma unroll
    for (int it = 0; it < 8; it++) {
        int chunk = tid + it * 256;          // 0..2047 (oc*8 + j)
        int oc = chunk >> 3, j = chunk & 7;
        uint32_t dst = bBase + (uint32_t)(oc * 144 + j * 16);
        asm volatile("cp.async.cg.shared.global [%0], [%1], 16, 16;"
                     :: "r"(dst), "l"(ws + chunk * 8));
    }
}

__global__ __launch_bounds__(256, 1)
void conv_hmma_kernel(const int* __restrict__ bias, float* __restrict__ out) {
    extern __shared__ __align__(16) char dsm[];
    const uint32_t sbase = smem_u32(dsm);
    float* sbias = (float*)(dsm + OFF_BIAS);

    const int tid = threadIdx.x;
    const int lane = tid & 31;
    const int wid  = tid >> 5;
    const int g    = lane >> 2;      // groupID 0..7
    const int tig  = lane & 3;       // thread-in-group 0..3
    const int wm   = wid & 1;        // 2 M tiles of 64 px
    const int wn   = wid >> 1;       // 4 N tiles of 64 oc
    const int p0   = blockIdx.x * MTILE;

    sbias[tid] = (float)bias[tid];

    float acc[4][8][4];
    #pragma unroll
    for (int i = 0; i < 4; i++)
        #pragma unroll
        for (int j = 0; j < 8; j++)
            #pragma unroll
            for (int r = 0; r < 4; r++) acc[i][j][r] = 0.0f;

    stage_copy(sbase, 0, 0, p0, tid);
    asm volatile("cp.async.commit_group;" ::: "memory");

    for (int s = 0; s < NSTAGE; s++) {
        asm volatile("cp.async.wait_group 0;" ::: "memory");
        __syncthreads();
        if (s + 1 < NSTAGE) {
            stage_copy(sbase, (s + 1) & 1, s + 1, p0, tid);
            asm volatile("cp.async.commit_group;" ::: "memory");
        }
        const int buf = s & 1;
        const unsigned* A = (const unsigned*)(dsm + OFF_A(buf));
        const unsigned* B = (const unsigned*)(dsm + OFF_B(buf));
        #pragma unroll
        for (int kq = 0; kq < 4; kq++) {
            const int koff = kq * 8;
            unsigned a[4][4];
            #pragma unroll
            for (int i = 0; i < 4; i++) {
                int r0 = wm * 64 + i * 16 + g;
                a[i][0] = A[r0 * RSTR + koff + tig];
                a[i][1] = A[(r0 + 8) * RSTR + koff + tig];
                a[i][2] = A[r0 * RSTR + koff + 4 + tig];
                a[i][3] = A[(r0 + 8) * RSTR + koff + 4 + tig];
            }
            unsigned bf[8][2];
            #pragma unroll
            for (int j = 0; j < 8; j++) {
                int c0 = wn * 64 + j * 8 + g;
                bf[j][0] = B[c0 * RSTR + koff + tig];
                bf[j][1] = B[c0 * RSTR + koff + 4 + tig];
            }
            #pragma unroll
            for (int i = 0; i < 4; i++)
                #pragma unroll
                for (int j = 0; j < 8; j++)
                    mma_bf16(acc[i][j], a[i], bf[j]);
        }
        __syncthreads();
    }

    // epilogue: +bias, float32 out (NCHW)
    #pragma unroll
    for (int i = 0; i < 4; i++) {
        int r = wm * 64 + i * 16 + g;
        int px0 = p0 + r, px1 = px0 + 8;
        int b0 = px0 / HW, rem0 = px0 - b0 * HW;
        int b1 = px1 / HW, rem1 = px1 - b1 * HW;
        float* base0 = out + (size_t)b0 * (OC * HW) + rem0;
        float* base1 = out + (size_t)b1 * (OC * HW) + rem1;
        #pragma unroll
        for (int j = 0; j < 8; j++) {
            int oc = wn * 64 + j * 8 + tig * 2;
            float bv0 = sbias[oc], bv1 = sbias[oc + 1];
            base0[(size_t)oc * HW]       = acc[i][j][0] + bv0;
            base0[(size_t)(oc + 1) * HW] = acc[i][j][1] + bv1;
            base1[(size_t)oc * HW]       = acc[i][j][2] + bv0;
            base1[(size_t)(oc + 1) * HW] = acc[i][j][3] + bv1;
        }
    }
}

extern "C" void kernel_launch(void* const* d_in, const int* in_sizes, int n_in,
                              void* d_out, int out_size) {
    const int* x    = nullptr;
    const int* wsrc = nullptr;
    const int* bias = nullptr;
    for (int i = 0; i < n_in; i++) {
        if (in_sizes[i] == X_ELEMS)      x    = (const int*)d_in[i];
        else if (in_sizes[i] == W_ELEMS) wsrc = (const int*)d_in[i];
        else if (in_sizes[i] == B_ELEMS) bias = (const int*)d_in[i];
    }
    if (!x)    x    = (const int*)d_in[0];
    if (!wsrc) wsrc = (const int*)d_in[1];
    if (!bias) bias = (const int*)d_in[2];

    float* out = (float*)d_out;

    pack_fused_kernel<<<(XWORK + WWORK + 255) / 256, 256>>>(x, wsrc);

    cudaFuncSetAttribute(conv_hmma_kernel,
                         cudaFuncAttributeMaxDynamicSharedMemorySize, SMEM_BYTES);
    conv_hmma_kernel<<<NBLK, 256, SMEM_BYTES>>>(bias, out);
}

// round 7
// speedup vs baseline: 3.4932x; 1.0892x over previous
#include <cuda_runtime.h>
#include <cuda_bf16.h>
#include <cstdint>

#define BN   16
#define C    256
#define H    56
#define W    56
#define OC   256
#define HW   (H*W)          // 3136
#define NPIX (BN*HW)        // 50176

#define X_ELEMS  (BN*C*H*W) // 12845056
#define W_ELEMS  (OC*C*3*3) // 589824
#define B_ELEMS  (OC)       // 256

#define NSTAGE 36           // 9 taps x 4 ic-planes (64 ic each)
#define MTILE  128          // output pixels per block
#define NBLK   (NPIX/MTILE) // 392
#define NTHR   512

#define RSTRB  144          // padded row stride in bytes (64 bf16 + 16B pad)
#define A_TILE (MTILE*RSTRB)    // 18432 B
#define B_TILE (OC*RSTRB)       // 36864 B
#define OFF_A(buf)  ((buf)*A_TILE)
#define OFF_B(buf)  (2*A_TILE + (buf)*B_TILE)
#define OFF_BIAS    (2*A_TILE + 2*B_TILE)
#define SMEM_BYTES  (OFF_BIAS + OC*4)       // 111616

// ---- packed bf16 scratch (device globals; allocation-free rule) ----
__device__ __nv_bfloat16 g_xb[NPIX * C];            // [pix][256 ic]
__device__ __nv_bfloat16 g_wb[NSTAGE * OC * 64];    // [stage][oc][64 ic]

#define XWORK (NPIX * 32)           // 8 channels per work item
#define WWORK (NSTAGE * OC * 64)    // == W_ELEMS

__global__ void pack_fused_kernel(const int* __restrict__ x,
                                  const int* __restrict__ wsrc) {
    int idx = blockIdx.x * blockDim.x + threadIdx.x;
    if (idx < XWORK) {
        int pix = idx % NPIX;
        int grp = idx / NPIX;
        int c0 = grp * 8;
        int w = pix % W;
        int t = pix / W;
        int h = t % H;
        int b = t / H;
        const int* p = x + ((b * C + c0) * H + h) * W + w;
        __align__(16) __nv_bfloat16 v[8];
        #pragma unroll
        for (int k = 0; k < 8; k++) v[k] = __float2bfloat16((float)p[k * HW]);
        *(uint4*)&g_xb[pix * C + c0] = *(const uint4*)v;
    } else if (idx < XWORK + WWORK) {
        int j = idx - XWORK;
        int i  = j & 63;
        int oc = (j >> 6) & 255;
        int s  = j >> 14;            // 0..35
        int tap = s >> 2, plane = s & 3;
        int ic = plane * 64 + i;
        g_wb[j] = __float2bfloat16((float)wsrc[(oc * C + ic) * 9 + tap]);
    }
}

__device__ __forceinline__ uint32_t smem_u32(const void* p) {
    uint32_t a;
    asm("{ .reg .u64 t; cvta.to.shared.u64 t, %1; cvt.u32.u64 %0, t; }" : "=r"(a) : "l"(p));
    return a;
}

__device__ __forceinline__ void mma_bf16(float* c, const unsigned* a, const unsigned* b) {
    asm volatile(
        "mma.sync.aligned.m16n8k16.row.col.f32.bf16.bf16.f32 "
        "{%0,%1,%2,%3}, {%4,%5,%6,%7}, {%8,%9}, {%0,%1,%2,%3};"
        : "+f"(c[0]), "+f"(c[1]), "+f"(c[2]), "+f"(c[3])
        : "r"(a[0]), "r"(a[1]), "r"(a[2]), "r"(a[3]), "r"(b[0]), "r"(b[1]));
}

#define LDSM_X4(r0, r1, r2, r3, addr)                                        \
    asm volatile("ldmatrix.sync.aligned.m8n8.x4.shared.b16 {%0,%1,%2,%3}, [%4];" \
        : "=r"(r0), "=r"(r1), "=r"(r2), "=r"(r3) : "r"(addr))

// stage copy: A[128px x 64ic bf16] with tap shift + zero halo, B[256oc x 64ic]
__device__ __forceinline__ void stage_copy(uint32_t sbase, int buf, int s,
                                           int p0, int tid) {
    const int tap = s >> 2, plane = s & 3;
    const int dh = tap / 3 - 1, dw = tap % 3 - 1;
    const uint32_t aBase = sbase + OFF_A(buf);
    #pragma unroll
    for (int it = 0; it < 2; it++) {
        int chunk = tid + it * NTHR;         // 0..1023
        int m = chunk >> 3, j = chunk & 7;   // pixel row, 16B chunk
        int p = p0 + m;
        int b = p / HW, rem = p - b * HW;
        int h = rem / W, w = rem - h * W;
        int h2 = h + dh, w2 = w + dw;
        bool ok = ((unsigned)h2 < (unsigned)H) && ((unsigned)w2 < (unsigned)W);
        int sp = ok ? ((b * H + h2) * W + w2) : 0;
        const __nv_bfloat16* src = &g_xb[sp * C + plane * 64 + j * 8];
        uint32_t dst = aBase + (uint32_t)(m * RSTRB + j * 16);
        int sz = ok ? 16 : 0;                // src-size 0 -> zero-fill
        asm volatile("cp.async.cg.shared.global [%0], [%1], 16, %2;"
                     :: "r"(dst), "l"(src), "r"(sz));
    }
    const uint32_t bBase = sbase + OFF_B(buf);
    const __nv_bfloat16* ws = &g_wb[s * OC * 64];
    #pragma unroll
    for (int it = 0; it < 4; it++) {
        int chunk = tid + it * NTHR;         // 0..2047 (oc*8 + j)
        int oc = chunk >> 3, j = chunk & 7;
        uint32_t dst = bBase + (uint32_t)(oc * RSTRB + j * 16);
        asm volatile("cp.async.cg.shared.global [%0], [%1], 16, 16;"
                     :: "r"(dst), "l"(ws + chunk * 8));
    }
}

__global__ __launch_bounds__(NTHR, 1)
void conv_hmma_kernel(const int* __restrict__ bias, float* __restrict__ out) {
    extern __shared__ __align__(16) char dsm[];
    const uint32_t sbase = smem_u32(dsm);
    float* sbias = (float*)(dsm + OFF_BIAS);

    const int tid = threadIdx.x;
    const int lane = tid & 31;
    const int wid  = tid >> 5;
    const int g    = lane >> 2;      // groupID 0..7
    const int tig  = lane & 3;       // thread-in-group 0..3
    const int wm   = wid & 3;        // 4 M tiles of 32 px
    const int wn   = wid >> 2;       // 4 N tiles of 64 oc
    const int p0   = blockIdx.x * MTILE;

    if (tid < OC) sbias[tid] = (float)bias[tid];

    // ldmatrix per-thread row offsets (in bytes, within a tile)
    // A x4: row = (lane&15), k16 = lane>>4
    const uint32_t aoff = (uint32_t)((wm * 32 + (lane & 15)) * RSTRB + ((lane >> 4) & 1) * 16);
    // B x4: oc = ((lane>>4)&1)*8 + (lane&7), k16 = (lane>>3)&1
    const uint32_t boff = (uint32_t)(((wn * 64) + ((lane >> 4) & 1) * 8 + (lane & 7)) * RSTRB
                                     + ((lane >> 3) & 1) * 16);

    float acc[2][8][4];
    #pragma unroll
    for (int i = 0; i < 2; i++)
        #pragma unroll
        for (int j = 0; j < 8; j++)
            #pragma unroll
            for (int r = 0; r < 4; r++) acc[i][j][r] = 0.0f;

    stage_copy(sbase, 0, 0, p0, tid);
    asm volatile("cp.async.commit_group;" ::: "memory");

    for (int s = 0; s < NSTAGE; s++) {
        asm volatile("cp.async.wait_group 0;" ::: "memory");
        __syncthreads();
        if (s + 1 < NSTAGE) {
            stage_copy(sbase, (s + 1) & 1, s + 1, p0, tid);
            asm volatile("cp.async.commit_group;" ::: "memory");
        }
        const int buf = s & 1;
        const uint32_t aT = sbase + OFF_A(buf) + aoff;
        const uint32_t bT = sbase + OFF_B(buf) + boff;
        #pragma unroll
        for (int kq = 0; kq < 4; kq++) {
            const uint32_t kb = (uint32_t)(kq * 32);
            unsigned a[2][4];
            #pragma unroll
            for (int i = 0; i < 2; i++)
                LDSM_X4(a[i][0], a[i][1], a[i][2], a[i][3],
                        aT + kb + (uint32_t)(i * 16 * RSTRB));
            unsigned bf[8][2];
            #pragma unroll
            for (int jp = 0; jp < 4; jp++)
                LDSM_X4(bf[2*jp][0], bf[2*jp][1], bf[2*jp+1][0], bf[2*jp+1][1],
                        bT + kb + (uint32_t)(jp * 16 * RSTRB));
            #pragma unroll
            for (int i = 0; i < 2; i++)
                #pragma unroll
                for (int j = 0; j < 8; j++)
                    mma_bf16(acc[i][j], a[i], bf[j]);
        }
        __syncthreads();
    }

    // epilogue: +bias, float32 out (NCHW)
    #pragma unroll
    for (int i = 0; i < 2; i++) {
        int r = wm * 32 + i * 16 + g;
        int px0 = p0 + r, px1 = px0 + 8;
        int b0 = px0 / HW, rem0 = px0 - b0 * HW;
        int b1 = px1 / HW, rem1 = px1 - b1 * HW;
        float* base0 = out + (size_t)b0 * (OC * HW) + rem0;
        float* base1 = out + (size_t)b1 * (OC * HW) + rem1;
        #pragma unroll
        for (int j = 0; j < 8; j++) {
            int oc = wn * 64 + j * 8 + tig * 2;
            float bv0 = sbias[oc], bv1 = sbias[oc + 1];
            base0[(size_t)oc * HW]       = acc[i][j][0] + bv0;
            base0[(size_t)(oc + 1) * HW] = acc[i][j][1] + bv1;
            base1[(size_t)oc * HW]       = acc[i][j][2] + bv0;
            base1[(size_t)(oc + 1) * HW] = acc[i][j][3] + bv1;
        }
    }
}

extern "C" void kernel_launch(void* const* d_in, const int* in_sizes, int n_in,
                              void* d_out, int out_size) {
    const int* x    = nullptr;
    const int* wsrc = nullptr;
    const int* bias = nullptr;
    for (int i = 0; i < n_in; i++) {
        if (in_sizes[i] == X_ELEMS)      x    = (const int*)d_in[i];
        else if (in_sizes[i] == W_ELEMS) wsrc = (const int*)d_in[i];
        else if (in_sizes[i] == B_ELEMS) bias = (const int*)d_in[i];
    }
    if (!x)    x    = (const int*)d_in[0];
    if (!wsrc) wsrc = (const int*)d_in[1];
    if (!bias) bias = (const int*)d_in[2];

    float* out = (float*)d_out;

    pack_fused_kernel<<<(XWORK + WWORK + 255) / 256, 256>>>(x, wsrc);

    cudaFuncSetAttribute(conv_hmma_kernel,
                         cudaFuncAttributeMaxDynamicSharedMemorySize, SMEM_BYTES);
    conv_hmma_kernel<<<NBLK, NTHR, SMEM_BYTES>>>(bias, out);
}